// round 3
// baseline (speedup 1.0000x reference)
#include <cuda_runtime.h>

#define NN  50000
#define NC  256
#define DD  64
#define HH  128
#define EVV 800000
#define EVC 400000

#define RB  16      // rows per tile in vertex MLP
#define TB  256     // threads per block in vertex MLP

// Scratch: precomputed per-node / per-color messages
__device__ float g_yv[NN * DD];   // 12.8 MB, L2-resident
__device__ float g_yc[NC * DD];   // 64 KB, L1-resident

// ---------------------------------------------------------------------------
// Kernel A: y_c = MLP_c(x_c) for all 256 colors. One block per color row.
// Weights read through L1/L2 (all blocks share the same 64 KB).
// ---------------------------------------------------------------------------
__global__ void __launch_bounds__(128) mlp_color_kernel(
    const float* __restrict__ x_c,
    const float* __restrict__ W1, const float* __restrict__ b1,
    const float* __restrict__ W2, const float* __restrict__ b2)
{
    __shared__ float xs[DD];
    __shared__ float hs[HH];
    const int row = blockIdx.x;
    const int t = threadIdx.x;            // 128 threads
    if (t < DD) xs[t] = x_c[row * DD + t];
    __syncthreads();
    float acc = b1[t];
#pragma unroll 16
    for (int k = 0; k < DD; k++) acc = fmaf(xs[k], W1[k * HH + t], acc);
    hs[t] = fmaxf(acc, 0.0f);
    __syncthreads();
    if (t < DD) {
        float a = b2[t];
#pragma unroll 16
        for (int j = 0; j < HH; j++) a = fmaf(hs[j], W2[j * DD + t], a);
        g_yc[row * DD + t] = a;
    }
}

// ---------------------------------------------------------------------------
// Kernel B: y_v = MLP_v(x_v) for all 50000 nodes, and out = x_v (accumulator
// init). Persistent blocks; weights cached in SMEM once per block; register
// tiling 2 rows x 4 cols (phase 1) / 1 row x 4 cols (phase 2), LDS.128 weights.
// ---------------------------------------------------------------------------
__global__ void __launch_bounds__(TB, 2) mlp_vertex_kernel(
    const float* __restrict__ x_v,
    const float* __restrict__ W1, const float* __restrict__ b1,
    const float* __restrict__ W2, const float* __restrict__ b2,
    float* __restrict__ out)
{
    extern __shared__ float sm[];
    float* W1s = sm;                 // 64*128 = 8192 floats
    float* W2s = W1s + DD * HH;      // 128*64 = 8192
    float* b1s = W2s + HH * DD;      // 128
    float* b2s = b1s + HH;           // 64
    float* xs  = b2s + DD;           // RB*64 = 1024
    float* hs  = xs + RB * DD;       // RB*128 = 2048
    const int t = threadIdx.x;

    // Load weights/biases into SMEM (once per block)
    {
        const float4* W14 = (const float4*)W1;
        float4* W1d = (float4*)W1s;
        for (int i = t; i < DD * HH / 4; i += TB) W1d[i] = W14[i];
        const float4* W24 = (const float4*)W2;
        float4* W2d = (float4*)W2s;
        for (int i = t; i < HH * DD / 4; i += TB) W2d[i] = W24[i];
        if (t < HH) b1s[t] = b1[t];
        if (t < DD) b2s[t] = b2[t];
    }

    const int ntiles = NN / RB;  // 3125 exactly
    for (int tile = blockIdx.x; tile < ntiles; tile += gridDim.x) {
        const int row0 = tile * RB;
        __syncthreads();   // weights visible (1st iter); xs/hs free (later iters)

        // Load x tile (16 rows x 64) + init accumulator out = x_v
        {
            const int r = t >> 4;          // 0..15
            const int q = t & 15;          // 0..15 (float4 index within row)
            float4 v = ((const float4*)x_v)[(size_t)(row0 + r) * (DD / 4) + q];
            ((float4*)xs)[r * (DD / 4) + q] = v;
            ((float4*)out)[(size_t)(row0 + r) * (DD / 4) + q] = v;
        }
        __syncthreads();

        // Phase 1: h[16][128] = relu(x @ W1 + b1)
        {
            const int warp = t >> 5;       // 0..7 -> rows warp, warp+8
            const int lane = t & 31;       // j-group: columns lane*4..lane*4+3
            const int r0 = warp, r1 = warp + 8;
            float4 bv = ((const float4*)b1s)[lane];
            float4 a0 = bv, a1 = bv;
            const float4* wp = (const float4*)W1s;
#pragma unroll 16
            for (int k = 0; k < DD; k++) {
                float4 w = wp[k * (HH / 4) + lane];
                float x0 = xs[r0 * DD + k];      // warp-uniform broadcast
                float x1 = xs[r1 * DD + k];
                a0.x = fmaf(w.x, x0, a0.x); a0.y = fmaf(w.y, x0, a0.y);
                a0.z = fmaf(w.z, x0, a0.z); a0.w = fmaf(w.w, x0, a0.w);
                a1.x = fmaf(w.x, x1, a1.x); a1.y = fmaf(w.y, x1, a1.y);
                a1.z = fmaf(w.z, x1, a1.z); a1.w = fmaf(w.w, x1, a1.w);
            }
            a0.x = fmaxf(a0.x, 0.f); a0.y = fmaxf(a0.y, 0.f);
            a0.z = fmaxf(a0.z, 0.f); a0.w = fmaxf(a0.w, 0.f);
            a1.x = fmaxf(a1.x, 0.f); a1.y = fmaxf(a1.y, 0.f);
            a1.z = fmaxf(a1.z, 0.f); a1.w = fmaxf(a1.w, 0.f);
            ((float4*)hs)[r0 * (HH / 4) + lane] = a0;
            ((float4*)hs)[r1 * (HH / 4) + lane] = a1;
        }
        __syncthreads();

        // Phase 2: y[16][64] = h @ W2 + b2 -> g_yv
        {
            const int r = t >> 4;          // 0..15
            const int dd = t & 15;         // column group dd*4..dd*4+3
            float4 a = ((const float4*)b2s)[dd];
            const float4* wp2 = (const float4*)W2s;
#pragma unroll 32
            for (int j = 0; j < HH; j++) {
                float4 w = wp2[j * (DD / 4) + dd];
                float hv = hs[r * HH + j];
                a.x = fmaf(w.x, hv, a.x); a.y = fmaf(w.y, hv, a.y);
                a.z = fmaf(w.z, hv, a.z); a.w = fmaf(w.w, hv, a.w);
            }
            ((float4*)g_yv)[(size_t)(row0 + r) * (DD / 4) + dd] = a;
        }
    }
}

// ---------------------------------------------------------------------------
// Kernel C/D: edge scatter. One thread per (edge, float4-chunk):
//   out[dst] += table[src]   (vector RED.128, no return value used)
// Table is L2-resident (y_v) or L1-resident (y_c).
// ---------------------------------------------------------------------------
__global__ void __launch_bounds__(256) scatter_kernel(
    const int* __restrict__ src, const int* __restrict__ dst,
    float* __restrict__ out, int nedges, int use_color)
{
    const int gid = blockIdx.x * blockDim.x + threadIdx.x;
    const int e = gid >> 4;
    if (e >= nedges) return;
    const int q = gid & 15;
    const float4* table = use_color ? (const float4*)g_yc : (const float4*)g_yv;
    float4 v = table[(size_t)src[e] * (DD / 4) + q];
    atomicAdd((float4*)out + (size_t)dst[e] * (DD / 4) + q, v);  // -> RED.128
}

// ---------------------------------------------------------------------------
// Kernel E: final out = relu(out)
// ---------------------------------------------------------------------------
__global__ void __launch_bounds__(256) relu_kernel(float* __restrict__ out)
{
    const int g = blockIdx.x * blockDim.x + threadIdx.x;
    if (g < NN * DD / 4) {
        float4 v = ((const float4*)out)[g];
        v.x = fmaxf(v.x, 0.f); v.y = fmaxf(v.y, 0.f);
        v.z = fmaxf(v.z, 0.f); v.w = fmaxf(v.w, 0.f);
        ((float4*)out)[g] = v;
    }
}

// ---------------------------------------------------------------------------
extern "C" void kernel_launch(void* const* d_in, const int* in_sizes, int n_in,
                              void* d_out, int out_size)
{
    const float* x_v  = (const float*)d_in[0];
    const float* x_c  = (const float*)d_in[1];
    const float* W1v  = (const float*)d_in[2];
    const float* b1v  = (const float*)d_in[3];
    const float* W2v  = (const float*)d_in[4];
    const float* b2v  = (const float*)d_in[5];
    const float* W1c  = (const float*)d_in[6];
    const float* b1c  = (const float*)d_in[7];
    const float* W2c  = (const float*)d_in[8];
    const float* b2c  = (const float*)d_in[9];
    const int* src_vv = (const int*)d_in[10];
    const int* dst_vv = (const int*)d_in[11];
    const int* src_vc = (const int*)d_in[12];
    const int* dst_vc = (const int*)d_in[13];
    float* out = (float*)d_out;

    const int smem_b = (DD * HH + HH * DD + HH + DD + RB * DD + RB * HH) * (int)sizeof(float);
    cudaFuncSetAttribute(mlp_vertex_kernel,
                         cudaFuncAttributeMaxDynamicSharedMemorySize, smem_b);

    // 1. Precompute color messages (256 rows)
    mlp_color_kernel<<<NC, 128>>>(x_c, W1c, b1c, W2c, b2c);
    // 2. Precompute vertex messages (50000 rows) + init out = x_v
    mlp_vertex_kernel<<<304, TB, smem_b>>>(x_v, W1v, b1v, W2v, b2v, out);
    // 3. Scatter v->v edges: out[dst] += y_v[src]
    scatter_kernel<<<(EVV * 16 + 255) / 256, 256>>>(src_vv, dst_vv, out, EVV, 0);
    // 4. Scatter c->v edges: out[dst] += y_c[src]
    scatter_kernel<<<(EVC * 16 + 255) / 256, 256>>>(src_vc, dst_vc, out, EVC, 1);
    // 5. Final ReLU
    relu_kernel<<<(NN * DD / 4 + 255) / 256, 256>>>(out);
}

// round 4
// speedup vs baseline: 1.2247x; 1.2247x over previous
#include <cuda_runtime.h>

#define NN  50000
#define NC  256
#define DD  64
#define HH  128
#define EVV 800000
#define EVC 400000
#define NE  (EVV + EVC)
#define SCAN_N (2 * NN)            // vv counters then vc counters
#define SCAN_BLOCKS ((SCAN_N + 1023) / 1024)   // 98

#define MLP_VBLOCKS 288            // vertex-MLP persistent blocks
#define MLP_GRID    (MLP_VBLOCKS + 8)  // +8 color blocks
#define NTILES_V    1563           // ceil(50000/32)

typedef unsigned long long ull;

// ---------------- scratch (device globals; no allocation) -------------------
__device__ float g_yv[NN * DD];        // per-vertex messages, 12.8 MB
__device__ float g_yc[NC * DD];        // per-color messages, 64 KB
__device__ int   d_cnt[SCAN_N];
__device__ int   d_ofs[SCAN_N + 1];
__device__ int   d_cur[SCAN_N];
__device__ int   d_srcs[NE];           // joint sorted-by-dst src lists
__device__ int   d_part[SCAN_BLOCKS];

// ---------------- f32x2 helpers --------------------------------------------
__device__ __forceinline__ ull pk2(float lo, float hi) {
    ull r; asm("mov.b64 %0, {%1, %2};" : "=l"(r) : "f"(lo), "f"(hi)); return r;
}
__device__ __forceinline__ void upk2(ull v, float& lo, float& hi) {
    asm("mov.b64 {%0, %1}, %2;" : "=f"(lo), "=f"(hi) : "l"(v));
}
__device__ __forceinline__ ull ffma2(ull a, ull b, ull c) {
    ull d; asm("fma.rn.f32x2 %0, %1, %2, %3;" : "=l"(d) : "l"(a), "l"(b), "l"(c)); return d;
}
__device__ __forceinline__ ull fadd2(ull a, ull b) {
    ull d; asm("add.rn.f32x2 %0, %1, %2;" : "=l"(d) : "l"(a), "l"(b)); return d;
}

// ---------------------------------------------------------------------------
// Fused MLP: y = relu(x@W1+b1)@W2+b2 for vertices (blocks 0..287, persistent)
// and colors (blocks 288..295). Tiling: 32 rows/tile, lane = row,
// warp = column group; weights broadcast from SMEM, f32x2 accumulators.
// ---------------------------------------------------------------------------
__global__ void __launch_bounds__(256, 2) mlp_kernel(
    const float* __restrict__ x_v,
    const float* __restrict__ x_c,
    const float* __restrict__ W1v, const float* __restrict__ b1v,
    const float* __restrict__ W2v, const float* __restrict__ b2v,
    const float* __restrict__ W1c, const float* __restrict__ b1c,
    const float* __restrict__ W2c, const float* __restrict__ b2c)
{
    extern __shared__ float sm[];
    float* W1s = sm;                     // [64][128]
    float* W2s = W1s + DD * HH;          // [128][64]
    float* b1s = W2s + HH * DD;          // [128]
    float* b2s = b1s + HH;               // [64]
    float* xs  = b2s + DD;               // [64][33]  x transposed (padded)
    ull*   hs  = (ull*)(xs + DD * 33);   // [128][33] h duplicated pairs

    const int t = threadIdx.x;
    const int lane = t & 31;
    const int warp = t >> 5;

    const bool is_color = (blockIdx.x >= MLP_VBLOCKS);
    const float *X, *W1, *B1, *W2, *B2;
    float* Y;
    int tile0, tstride, ntile, nrows;
    if (!is_color) {
        X = x_v; Y = g_yv; W1 = W1v; B1 = b1v; W2 = W2v; B2 = b2v;
        tile0 = blockIdx.x; tstride = MLP_VBLOCKS; ntile = NTILES_V; nrows = NN;
    } else {
        X = x_c; Y = g_yc; W1 = W1c; B1 = b1c; W2 = W2c; B2 = b2c;
        tile0 = blockIdx.x - MLP_VBLOCKS; tstride = 8; ntile = 8; nrows = NC;
    }

    // cache weights in SMEM (once per block)
    {
        const float4* s1 = (const float4*)W1;
        float4* d1 = (float4*)W1s;
        for (int i = t; i < DD * HH / 4; i += 256) d1[i] = s1[i];
        const float4* s2 = (const float4*)W2;
        float4* d2 = (float4*)W2s;
        for (int i = t; i < HH * DD / 4; i += 256) d2[i] = s2[i];
        if (t < HH) b1s[t] = B1[t];
        if (t < DD) b2s[t] = B2[t];
    }

    for (int tile = tile0; tile < ntile; tile += tstride) {
        const int row0 = tile * 32;
        __syncthreads();   // weights visible / previous tile done with buffers

        // load x tile (32 rows x 64) transposed into xs[k][row]
        {
            const int r = t >> 3;       // 0..31
            const int q = t & 7;        // float4 index half
            const int row = row0 + r;
#pragma unroll
            for (int h = 0; h < 2; h++) {
                const int q4 = q + 8 * h;        // 0..15
                float4 v = make_float4(0.f, 0.f, 0.f, 0.f);
                if (row < nrows) v = ((const float4*)X)[row * 16 + q4];
                xs[(4 * q4 + 0) * 33 + r] = v.x;
                xs[(4 * q4 + 1) * 33 + r] = v.y;
                xs[(4 * q4 + 2) * 33 + r] = v.z;
                xs[(4 * q4 + 3) * 33 + r] = v.w;
            }
        }
        __syncthreads();

        // phase 1: h[row][c] = relu(x@W1+b1); row = lane, warp covers 16 cols
        {
            const int c0 = warp * 16;
            ull acc[8];
#pragma unroll
            for (int p = 0; p < 8; p++)
                acc[p] = *(const ull*)(b1s + c0 + 2 * p);
#pragma unroll 4
            for (int k = 0; k < DD; k++) {
                const float xv = xs[k * 33 + lane];
                const ull xp = pk2(xv, xv);
                const ull* wrow = (const ull*)(W1s + k * HH + c0);
#pragma unroll
                for (int p = 0; p < 8; p++)
                    acc[p] = ffma2(wrow[p], xp, acc[p]);
            }
#pragma unroll
            for (int p = 0; p < 8; p++) {
                float lo, hi; upk2(acc[p], lo, hi);
                lo = fmaxf(lo, 0.f); hi = fmaxf(hi, 0.f);
                hs[(c0 + 2 * p + 0) * 33 + lane] = pk2(lo, lo);
                hs[(c0 + 2 * p + 1) * 33 + lane] = pk2(hi, hi);
            }
        }
        __syncthreads();

        // phase 2: y[row][c] = h@W2+b2; row = lane, warp covers 8 cols
        {
            const int c0 = warp * 8;
            ull acc[4];
#pragma unroll
            for (int p = 0; p < 4; p++)
                acc[p] = *(const ull*)(b2s + c0 + 2 * p);
#pragma unroll 4
            for (int j = 0; j < HH; j++) {
                const ull hp = hs[j * 33 + lane];
                const ull* wrow = (const ull*)(W2s + j * DD + c0);
#pragma unroll
                for (int p = 0; p < 4; p++)
                    acc[p] = ffma2(wrow[p], hp, acc[p]);
            }
            const int row = row0 + lane;
            if (row < nrows) {
                float a0, a1, a2, a3, a4, a5, a6, a7;
                upk2(acc[0], a0, a1); upk2(acc[1], a2, a3);
                upk2(acc[2], a4, a5); upk2(acc[3], a6, a7);
                float4* yp = (float4*)(Y + row * DD + c0);
                yp[0] = make_float4(a0, a1, a2, a3);
                yp[1] = make_float4(a4, a5, a6, a7);
            }
        }
    }
}

// ---------------------------------------------------------------------------
// CSR build: zero counts -> histogram -> block scan -> base add -> fill
// ---------------------------------------------------------------------------
__global__ void __launch_bounds__(256) zero_cnt_kernel()
{
    const int i = blockIdx.x * 256 + threadIdx.x;
    if (i < SCAN_N) d_cnt[i] = 0;
}

__global__ void __launch_bounds__(256) hist_kernel(
    const int* __restrict__ dst_vv, const int* __restrict__ dst_vc)
{
    const int g = blockIdx.x * 256 + threadIdx.x;
    if (g < EVV) {
        atomicAdd(&d_cnt[dst_vv[g]], 1);
    } else if (g < NE) {
        atomicAdd(&d_cnt[NN + dst_vc[g - EVV]], 1);
    }
}

__global__ void __launch_bounds__(1024) scan1_kernel()
{
    __shared__ int s[1024];
    const int tid = threadIdx.x;
    const int i = blockIdx.x * 1024 + tid;
    const int v = (i < SCAN_N) ? d_cnt[i] : 0;
    s[tid] = v;
    __syncthreads();
#pragma unroll
    for (int off = 1; off < 1024; off <<= 1) {
        int a = (tid >= off) ? s[tid - off] : 0;
        __syncthreads();
        s[tid] += a;
        __syncthreads();
    }
    if (i < SCAN_N) d_ofs[i] = s[tid] - v;   // exclusive, block-local
    if (tid == 1023) d_part[blockIdx.x] = s[1023];
}

__global__ void __launch_bounds__(128) scan2_kernel()
{
    __shared__ int sp[128];
    const int tid = threadIdx.x;
    const int b = blockIdx.x;
    int loc = 0;
    for (int i = tid; i < b; i += 128) loc += d_part[i];
    sp[tid] = loc;
    __syncthreads();
#pragma unroll
    for (int off = 64; off > 0; off >>= 1) {
        if (tid < off) sp[tid] += sp[tid + off];
        __syncthreads();
    }
    const int base = sp[0];
    for (int i = tid; i < 1024; i += 128) {
        const int idx = b * 1024 + i;
        if (idx < SCAN_N) {
            const int o = d_ofs[idx] + base;
            d_ofs[idx] = o;
            d_cur[idx] = o;
        }
    }
    if (b == 0 && tid == 0) d_ofs[SCAN_N] = NE;
}

__global__ void __launch_bounds__(256) fill_kernel(
    const int* __restrict__ src_vv, const int* __restrict__ dst_vv,
    const int* __restrict__ src_vc, const int* __restrict__ dst_vc)
{
    const int g = blockIdx.x * 256 + threadIdx.x;
    if (g < EVV) {
        const int d = dst_vv[g];
        const int p = atomicAdd(&d_cur[d], 1);
        d_srcs[p] = src_vv[g];
    } else if (g < NE) {
        const int e = g - EVV;
        const int d = dst_vc[e];
        const int p = atomicAdd(&d_cur[NN + d], 1);
        d_srcs[p] = src_vc[e];
    }
}

// ---------------------------------------------------------------------------
// Gather: one warp per vertex. acc = x_v[v]; += y_v[src] over vv in-edges
// (streaming loads, y_v is L2-resident); += y_c[src] over vc in-edges
// (y_c stays L1-hot); out[v] = relu(acc). No atomics, coalesced I/O.
// ---------------------------------------------------------------------------
__global__ void __launch_bounds__(256) gather_kernel(
    const float* __restrict__ x_v, float* __restrict__ out)
{
    const int v = blockIdx.x * 8 + (threadIdx.x >> 5);   // grid*8 == NN exactly
    const int lane = threadIdx.x & 31;

    ull acc = ((const ull*)x_v)[v * 32 + lane];          // cols (2*lane, 2*lane+1)

    // vertex->vertex in-edges
    {
        const int a = d_ofs[v];
        const int b = d_ofs[v + 1];
        const ull* yv = (const ull*)g_yv;
        int e = a;
        for (; e + 8 <= b; e += 8) {
            int ss[8]; ull tt[8];
#pragma unroll
            for (int i = 0; i < 8; i++) ss[i] = d_srcs[e + i];
#pragma unroll
            for (int i = 0; i < 8; i++) tt[i] = __ldcs(yv + ss[i] * 32 + lane);
#pragma unroll
            for (int i = 0; i < 8; i++) acc = fadd2(acc, tt[i]);
        }
        for (; e < b; e++) {
            const int s = d_srcs[e];
            acc = fadd2(acc, __ldcs(yv + s * 32 + lane));
        }
    }

    // color->vertex in-edges
    {
        const int a = d_ofs[NN + v];
        const int b = d_ofs[NN + v + 1];
        const ull* yc = (const ull*)g_yc;
        int e = a;
        for (; e + 4 <= b; e += 4) {
            int ss[4]; ull tt[4];
#pragma unroll
            for (int i = 0; i < 4; i++) ss[i] = d_srcs[e + i];
#pragma unroll
            for (int i = 0; i < 4; i++) tt[i] = __ldg(yc + ss[i] * 32 + lane);
#pragma unroll
            for (int i = 0; i < 4; i++) acc = fadd2(acc, tt[i]);
        }
        for (; e < b; e++) {
            const int s = d_srcs[e];
            acc = fadd2(acc, __ldg(yc + s * 32 + lane));
        }
    }

    float lo, hi; upk2(acc, lo, hi);
    ((float2*)out)[v * 32 + lane] = make_float2(fmaxf(lo, 0.f), fmaxf(hi, 0.f));
}

// ---------------------------------------------------------------------------
extern "C" void kernel_launch(void* const* d_in, const int* in_sizes, int n_in,
                              void* d_out, int out_size)
{
    const float* x_v  = (const float*)d_in[0];
    const float* x_c  = (const float*)d_in[1];
    const float* W1v  = (const float*)d_in[2];
    const float* b1v  = (const float*)d_in[3];
    const float* W2v  = (const float*)d_in[4];
    const float* b2v  = (const float*)d_in[5];
    const float* W1c  = (const float*)d_in[6];
    const float* b1c  = (const float*)d_in[7];
    const float* W2c  = (const float*)d_in[8];
    const float* b2c  = (const float*)d_in[9];
    const int* src_vv = (const int*)d_in[10];
    const int* dst_vv = (const int*)d_in[11];
    const int* src_vc = (const int*)d_in[12];
    const int* dst_vc = (const int*)d_in[13];
    float* out = (float*)d_out;

    const int smem_b = (DD * HH + HH * DD + HH + DD + DD * 33) * (int)sizeof(float)
                     + HH * 33 * (int)sizeof(ull);   // 108544 bytes
    cudaFuncSetAttribute(mlp_kernel,
                         cudaFuncAttributeMaxDynamicSharedMemorySize, smem_b);

    // CSR build (independent of MLP)
    zero_cnt_kernel<<<(SCAN_N + 255) / 256, 256>>>();
    hist_kernel<<<(NE + 255) / 256, 256>>>(dst_vv, dst_vc);
    scan1_kernel<<<SCAN_BLOCKS, 1024>>>();
    scan2_kernel<<<SCAN_BLOCKS, 128>>>();
    fill_kernel<<<(NE + 255) / 256, 256>>>(src_vv, dst_vv, src_vc, dst_vc);

    // per-node / per-color messages (vertex + color fused)
    mlp_kernel<<<MLP_GRID, 256, smem_b>>>(x_v, x_c, W1v, b1v, W2v, b2v,
                                          W1c, b1c, W2c, b2c);

    // final gather + residual + relu
    gather_kernel<<<NN / 8, 256>>>(x_v, out);
}